// round 1
// baseline (speedup 1.0000x reference)
#include <cuda_runtime.h>

// ---------------------------------------------------------------------------
// SE3Net: all irreps are l=0, so the per-pair kernel K(r) is a pure function
// of the scalar distance r, and the bias-free radial MLP is identically zero
// for r >= 4.5 (outside the cosine-bump support). Strategy:
//   Kernel 1: tabulate R(r) (46 outputs) on a 1024-point grid over [0, 4.5],
//             running the 50-layer MLP exactly in fp32 (packed f32x2 FFMA).
//   Kernel 2: pairwise conv via linear interpolation of the table + dot with
//             features, producing relu(out[b,i,o]).
//   Kernel 3: mean over atoms + final linear layer -> d_out[B].
// ---------------------------------------------------------------------------

#define NPTS    1024
#define OC      46          // C_OUT * C_IN
#define CIN     23
#define NB      286
#define BATCH   4
#define HDIM    100
#define NLAYERS 49          // hidden->hidden layers (L-1)
#define RMAX    4.5f
#define DELTA   (RMAX / (float)(NPTS - 1))
#define INV_DELTA ((float)(NPTS - 1) / RMAX)

#define TM 8                // grid rows per MLP block
#define RP (TM / 2)         // row pairs (f32x2 packing)

__device__ float g_table[NPTS * OC];           // tabulated K(r), scale folded in
__device__ float g_rows[BATCH * NB * 2];       // relu(out[b,i,o])

// ---- packed fp32x2 helpers (Blackwell FFMA2) ------------------------------
__device__ __forceinline__ unsigned long long ffma2(unsigned long long a,
                                                    unsigned long long b,
                                                    unsigned long long c) {
    unsigned long long d;
    asm("fma.rn.f32x2 %0, %1, %2, %3;" : "=l"(d) : "l"(a), "l"(b), "l"(c));
    return d;
}
__device__ __forceinline__ unsigned long long pack2(float lo, float hi) {
    unsigned long long d;
    asm("mov.b64 %0, {%1, %2};" : "=l"(d) : "f"(lo), "f"(hi));
    return d;
}
__device__ __forceinline__ float2 unpack2(unsigned long long v) {
    float lo, hi;
    asm("mov.b64 {%0, %1}, %2;" : "=f"(lo), "=f"(hi) : "l"(v));
    return make_float2(lo, hi);
}

__device__ __forceinline__ float bump(float x) {
    float ax = fabsf(x);
    if (ax >= 1.0f) return 0.0f;
    float c = cosf(1.5707963267948966f * x);
    return c * c;
}

// ---------------------------------------------------------------------------
// Kernel 1: grid MLP. Each block owns TM grid rows through all layers.
// h stored in SMEM as row-pair float2 so an LDS.128 yields two packed f32x2
// operands; W broadcast per output column via coalesced LDG.
// ---------------------------------------------------------------------------
__global__ void __launch_bounds__(128) mlp_table_kernel(
    const float* __restrict__ w_in,    // [3,100]
    const float* __restrict__ w_h,     // [49,100,100]
    const float* __restrict__ w_out)   // [100,46]
{
    __shared__ __align__(16) float2 h2[2][RP][HDIM];
    const int tid = threadIdx.x;
    const int m0 = blockIdx.x * TM;

    // ---- layer 0: basis -> h0 ----
    if (tid < HDIM) {
        const float inv_sqrt3 = 0.57735026918962576f;
        float wi0 = w_in[tid], wi1 = w_in[HDIM + tid], wi2 = w_in[2 * HDIM + tid];
        float v[TM];
#pragma unroll
        for (int r = 0; r < TM; r++) {
            float rr = (float)(m0 + r) * DELTA;
            float b0 = bump(rr * (1.0f / 1.5f));
            float b1 = bump((rr - 1.5f) * (1.0f / 1.5f));
            float b2 = bump((rr - 3.0f) * (1.0f / 1.5f));
            float a = (b0 * wi0 + b1 * wi1 + b2 * wi2) * inv_sqrt3;
            v[r] = fmaxf(a, 0.0f);
        }
#pragma unroll
        for (int p = 0; p < RP; p++)
            h2[0][p][tid] = make_float2(v[2 * p], v[2 * p + 1]);
    }
    __syncthreads();

    // ---- 49 hidden layers ----
    int cur = 0;
#pragma unroll 1
    for (int l = 0; l < NLAYERS; l++) {
        const float* __restrict__ W = w_h + l * (HDIM * HDIM);
        if (tid < HDIM) {
            unsigned long long acc[RP];
#pragma unroll
            for (int p = 0; p < RP; p++) acc[p] = 0ULL;
#pragma unroll
            for (int j = 0; j < HDIM; j += 4) {
                float w0 = W[(j + 0) * HDIM + tid];
                float w1 = W[(j + 1) * HDIM + tid];
                float w2 = W[(j + 2) * HDIM + tid];
                float w3 = W[(j + 3) * HDIM + tid];
                unsigned long long p0 = pack2(w0, w0);
                unsigned long long p1 = pack2(w1, w1);
                unsigned long long p2 = pack2(w2, w2);
                unsigned long long p3 = pack2(w3, w3);
#pragma unroll
                for (int p = 0; p < RP; p++) {
                    const ulonglong2* hp =
                        reinterpret_cast<const ulonglong2*>(&h2[cur][p][j]);
                    ulonglong2 ha = hp[0];   // pairs at j, j+1
                    ulonglong2 hb = hp[1];   // pairs at j+2, j+3
                    acc[p] = ffma2(ha.x, p0, acc[p]);
                    acc[p] = ffma2(ha.y, p1, acc[p]);
                    acc[p] = ffma2(hb.x, p2, acc[p]);
                    acc[p] = ffma2(hb.y, p3, acc[p]);
                }
            }
#pragma unroll
            for (int p = 0; p < RP; p++) {
                float2 v = unpack2(acc[p]);
                h2[cur ^ 1][p][tid] = make_float2(fmaxf(v.x * 0.1f, 0.0f),
                                                  fmaxf(v.y * 0.1f, 0.0f));
            }
        }
        __syncthreads();
        cur ^= 1;
    }

    // ---- output layer -> table (fold 1/sqrt(H), Y00, 1/sqrt(n_norm)) ----
    if (tid < OC) {
        unsigned long long acc[RP];
#pragma unroll
        for (int p = 0; p < RP; p++) acc[p] = 0ULL;
#pragma unroll
        for (int j = 0; j < HDIM; j += 2) {
            float w0 = w_out[(j + 0) * OC + tid];
            float w1 = w_out[(j + 1) * OC + tid];
            unsigned long long p0 = pack2(w0, w0);
            unsigned long long p1 = pack2(w1, w1);
#pragma unroll
            for (int p = 0; p < RP; p++) {
                ulonglong2 hv =
                    *reinterpret_cast<const ulonglong2*>(&h2[cur][p][j]);
                acc[p] = ffma2(hv.x, p0, acc[p]);
                acc[p] = ffma2(hv.y, p1, acc[p]);
            }
        }
        const float SCALE = 0.1f * 0.28209479177387814f * 0.5f; // /sqrt(H)*Y00/sqrt(4)
#pragma unroll
        for (int p = 0; p < RP; p++) {
            float2 v = unpack2(acc[p]);
            g_table[(m0 + 2 * p) * OC + tid]     = v.x * SCALE;
            g_table[(m0 + 2 * p + 1) * OC + tid] = v.y * SCALE;
        }
    }
}

// ---------------------------------------------------------------------------
// Kernel 2: pairwise conv. Block = (atom i, batch b); threads split neighbors.
// Features + geometry of batch b staged in SMEM (stride 23/3: conflict-free).
// Table rows hit L1/L2 (188 KB total).
// ---------------------------------------------------------------------------
__global__ void __launch_bounds__(256) conv_kernel(
    const float* __restrict__ features,   // [B,N,23]
    const float* __restrict__ geometry)   // [B,N,3]
{
    __shared__ float feat_s[NB * CIN];
    __shared__ float geo_s[NB * 3];
    __shared__ float red0[256];
    __shared__ float red1[256];

    const int i = blockIdx.x;
    const int b = blockIdx.y;
    const int tid = threadIdx.x;

    const float* fb = features + (size_t)b * NB * CIN;
    const float* gb = geometry + (size_t)b * NB * 3;
    for (int k = tid; k < NB * CIN; k += 256) feat_s[k] = fb[k];
    for (int k = tid; k < NB * 3; k += 256) geo_s[k] = gb[k];
    __syncthreads();

    const float gx = geo_s[i * 3 + 0];
    const float gy = geo_s[i * 3 + 1];
    const float gz = geo_s[i * 3 + 2];

    float acc0 = 0.0f, acc1 = 0.0f;
    for (int j = tid; j < NB; j += 256) {
        float dx = geo_s[j * 3 + 0] - gx;
        float dy = geo_s[j * 3 + 1] - gy;
        float dz = geo_s[j * 3 + 2] - gz;
        float r = sqrtf(fmaf(dx, dx, fmaf(dy, dy, fmaf(dz, dz, 1e-12f))));
        float t = r * INV_DELTA;
        int u = (int)t;
        if (u < NPTS - 1) {            // r >= 4.5 -> R == 0 exactly
            float w = t - (float)u;
            const float* __restrict__ T0 = g_table + u * OC;
            const float* __restrict__ T1 = T0 + OC;
            const float* fj = feat_s + j * CIN;
            float d00 = 0.f, d01 = 0.f, d10 = 0.f, d11 = 0.f;
#pragma unroll
            for (int c = 0; c < CIN; c++) {
                float fc = fj[c];
                d00 = fmaf(T0[c],        fc, d00);
                d01 = fmaf(T0[CIN + c],  fc, d01);
                d10 = fmaf(T1[c],        fc, d10);
                d11 = fmaf(T1[CIN + c],  fc, d11);
            }
            acc0 += fmaf(w, d10 - d00, d00);
            acc1 += fmaf(w, d11 - d01, d01);
        }
    }

    red0[tid] = acc0; red1[tid] = acc1;
    __syncthreads();
#pragma unroll
    for (int s = 128; s > 0; s >>= 1) {
        if (tid < s) { red0[tid] += red0[tid + s]; red1[tid] += red1[tid + s]; }
        __syncthreads();
    }
    if (tid == 0) {
        g_rows[(b * NB + i) * 2 + 0] = fmaxf(red0[0], 0.0f);
        g_rows[(b * NB + i) * 2 + 1] = fmaxf(red1[0], 0.0f);
    }
}

// ---------------------------------------------------------------------------
// Kernel 3: AvgSpacial + final linear. Deterministic fixed-order reduce.
// ---------------------------------------------------------------------------
__global__ void __launch_bounds__(128) final_kernel(
    const float* __restrict__ lin_w,   // [2]
    const float* __restrict__ lin_b,   // [1]
    float* __restrict__ out)           // [B]
{
    __shared__ float red0[128];
    __shared__ float red1[128];
    const int b = blockIdx.x;
    const int tid = threadIdx.x;
    float s0 = 0.f, s1 = 0.f;
    for (int i = tid; i < NB; i += 128) {
        s0 += g_rows[(b * NB + i) * 2 + 0];
        s1 += g_rows[(b * NB + i) * 2 + 1];
    }
    red0[tid] = s0; red1[tid] = s1;
    __syncthreads();
#pragma unroll
    for (int s = 64; s > 0; s >>= 1) {
        if (tid < s) { red0[tid] += red0[tid + s]; red1[tid] += red1[tid + s]; }
        __syncthreads();
    }
    if (tid == 0) {
        out[b] = (red0[0] * lin_w[0] + red1[0] * lin_w[1]) * (1.0f / (float)NB)
                 + lin_b[0];
    }
}

// ---------------------------------------------------------------------------
extern "C" void kernel_launch(void* const* d_in, const int* in_sizes, int n_in,
                              void* d_out, int out_size) {
    // Inputs (metadata order): features, geometry, [num_atoms], w_in,
    // w_hidden, w_out, lin_w, lin_b. Tolerate num_atoms being absent.
    int o = 0;
    if (n_in >= 4 && in_sizes[2] == 1) o = 1;   // num_atoms scalar present

    const float* features = (const float*)d_in[0];
    const float* geometry = (const float*)d_in[1];
    const float* w_in     = (const float*)d_in[2 + o];
    const float* w_h      = (const float*)d_in[3 + o];
    const float* w_out    = (const float*)d_in[4 + o];
    const float* lin_w    = (const float*)d_in[5 + o];
    const float* lin_b    = (const float*)d_in[6 + o];

    mlp_table_kernel<<<NPTS / TM, 128>>>(w_in, w_h, w_out);
    conv_kernel<<<dim3(NB, BATCH), 256>>>(features, geometry);
    final_kernel<<<BATCH, 128>>>(lin_w, lin_b, (float*)d_out);
}

// round 2
// speedup vs baseline: 2.9541x; 2.9541x over previous
#include <cuda_runtime.h>
#include <cstdint>

// ---------------------------------------------------------------------------
// SE3Net (all l=0): per-pair kernel K(r) is a scalar function of distance,
// zero for r >= 4.5. Tabulate on 256 points, interpolate in the conv.
//   Kernel 1: grid MLP, weights cp.async-double-buffered in SMEM,
//             packed f32x2 FFMA, 64 blocks x 128 threads, 4 rows/block.
//   Kernel 2: pairwise conv with interleaved table rows (LDG.64).
//   Kernel 3: mean + final linear.
// ---------------------------------------------------------------------------

#define NPTS    256
#define OC      46          // C_OUT * C_IN
#define OCP     48          // padded/interleaved table row stride (floats)
#define CIN     23
#define NB      286
#define BATCH   4
#define HDIM    100
#define NLAYERS 49
#define RMAX    4.5f
#define DELTA   (RMAX / (float)(NPTS - 1))
#define INV_DELTA ((float)(NPTS - 1) / RMAX)

#define TM 4                // grid rows per MLP block
#define RP (TM / 2)         // row pairs (f32x2 packing)
#define GRID_MLP (NPTS / TM)

__device__ float g_table[NPTS * OCP];          // interleaved: [u][c*2 + o]
__device__ float g_rows[BATCH * NB * 2];       // relu(out[b,i,o])

// ---- packed fp32x2 helpers (Blackwell FFMA2) ------------------------------
__device__ __forceinline__ unsigned long long ffma2(unsigned long long a,
                                                    unsigned long long b,
                                                    unsigned long long c) {
    unsigned long long d;
    asm("fma.rn.f32x2 %0, %1, %2, %3;" : "=l"(d) : "l"(a), "l"(b), "l"(c));
    return d;
}
__device__ __forceinline__ unsigned long long pack2(float lo, float hi) {
    unsigned long long d;
    asm("mov.b64 %0, {%1, %2};" : "=l"(d) : "f"(lo), "f"(hi));
    return d;
}
__device__ __forceinline__ float2 unpack2(unsigned long long v) {
    float lo, hi;
    asm("mov.b64 {%0, %1}, %2;" : "=f"(lo), "=f"(hi) : "l"(v));
    return make_float2(lo, hi);
}

__device__ __forceinline__ void cp16(void* smem_dst, const void* gptr) {
    uint32_t saddr = (uint32_t)__cvta_generic_to_shared(smem_dst);
    asm volatile("cp.async.cg.shared.global [%0], [%1], 16;"
                 :: "r"(saddr), "l"(gptr) : "memory");
}

__device__ __forceinline__ float bump(float x) {
    float ax = fabsf(x);
    if (ax >= 1.0f) return 0.0f;
    float c = cosf(1.5707963267948966f * x);
    return c * c;
}

// ---------------------------------------------------------------------------
// Kernel 1: grid MLP with SMEM-staged weights (double buffer, cp.async).
// ---------------------------------------------------------------------------
extern __shared__ float wbuf[];   // 2 * HDIM*HDIM floats = 80 KB

__global__ void __launch_bounds__(128) mlp_table_kernel(
    const float* __restrict__ w_in,    // [3,100]
    const float* __restrict__ w_h,     // [49,100,100]
    const float* __restrict__ w_out)   // [100,46]
{
    __shared__ __align__(16) float2 h2[2][RP][HDIM];
    const int tid = threadIdx.x;
    const int m0 = blockIdx.x * TM;

    float* buf0 = wbuf;
    float* buf1 = wbuf + HDIM * HDIM;

    // stage layer 0 weights
    for (int k = tid; k < (HDIM * HDIM) / 4; k += 128)
        cp16(buf0 + 4 * k, w_h + 4 * k);
    asm volatile("cp.async.commit_group;" ::: "memory");

    // ---- layer 0: basis -> h0 ----
    if (tid < HDIM) {
        const float inv_sqrt3 = 0.57735026918962576f;
        float wi0 = w_in[tid], wi1 = w_in[HDIM + tid], wi2 = w_in[2 * HDIM + tid];
        float v[TM];
#pragma unroll
        for (int r = 0; r < TM; r++) {
            float rr = (float)(m0 + r) * DELTA;
            float b0 = bump(rr * (1.0f / 1.5f));
            float b1 = bump((rr - 1.5f) * (1.0f / 1.5f));
            float b2 = bump((rr - 3.0f) * (1.0f / 1.5f));
            float a = (b0 * wi0 + b1 * wi1 + b2 * wi2) * inv_sqrt3;
            v[r] = fmaxf(a, 0.0f);
        }
#pragma unroll
        for (int p = 0; p < RP; p++)
            h2[0][p][tid] = make_float2(v[2 * p], v[2 * p + 1]);
    }
    __syncthreads();

    // ---- 49 hidden layers, double-buffered weights ----
    int cur = 0;
#pragma unroll 1
    for (int l = 0; l < NLAYERS; l++) {
        if (l + 1 < NLAYERS) {
            const float* src = w_h + (size_t)(l + 1) * (HDIM * HDIM);
            float* dst = ((l + 1) & 1) ? buf1 : buf0;
            for (int k = tid; k < (HDIM * HDIM) / 4; k += 128)
                cp16(dst + 4 * k, src + 4 * k);
            asm volatile("cp.async.commit_group;" ::: "memory");
            asm volatile("cp.async.wait_group 1;" ::: "memory");
        } else {
            asm volatile("cp.async.wait_group 0;" ::: "memory");
        }
        __syncthreads();

        const float* __restrict__ ws = (l & 1) ? buf1 : buf0;
        if (tid < HDIM) {
            unsigned long long acc[RP];
#pragma unroll
            for (int p = 0; p < RP; p++) acc[p] = 0ULL;
#pragma unroll
            for (int j = 0; j < HDIM; j += 4) {
                float w0 = ws[(j + 0) * HDIM + tid];
                float w1 = ws[(j + 1) * HDIM + tid];
                float w2 = ws[(j + 2) * HDIM + tid];
                float w3 = ws[(j + 3) * HDIM + tid];
                unsigned long long p0 = pack2(w0, w0);
                unsigned long long p1 = pack2(w1, w1);
                unsigned long long p2 = pack2(w2, w2);
                unsigned long long p3 = pack2(w3, w3);
#pragma unroll
                for (int p = 0; p < RP; p++) {
                    const ulonglong2* hp =
                        reinterpret_cast<const ulonglong2*>(&h2[cur][p][j]);
                    ulonglong2 ha = hp[0];   // f32x2 pairs at j, j+1
                    ulonglong2 hb = hp[1];   // pairs at j+2, j+3
                    acc[p] = ffma2(ha.x, p0, acc[p]);
                    acc[p] = ffma2(ha.y, p1, acc[p]);
                    acc[p] = ffma2(hb.x, p2, acc[p]);
                    acc[p] = ffma2(hb.y, p3, acc[p]);
                }
            }
#pragma unroll
            for (int p = 0; p < RP; p++) {
                float2 v = unpack2(acc[p]);
                h2[cur ^ 1][p][tid] = make_float2(fmaxf(v.x * 0.1f, 0.0f),
                                                  fmaxf(v.y * 0.1f, 0.0f));
            }
        }
        __syncthreads();
        cur ^= 1;
    }

    // ---- output layer -> interleaved table ----
    if (tid < OC) {
        unsigned long long acc[RP];
#pragma unroll
        for (int p = 0; p < RP; p++) acc[p] = 0ULL;
#pragma unroll
        for (int j = 0; j < HDIM; j += 2) {
            float w0 = w_out[(j + 0) * OC + tid];
            float w1 = w_out[(j + 1) * OC + tid];
            unsigned long long p0 = pack2(w0, w0);
            unsigned long long p1 = pack2(w1, w1);
#pragma unroll
            for (int p = 0; p < RP; p++) {
                ulonglong2 hv =
                    *reinterpret_cast<const ulonglong2*>(&h2[cur][p][j]);
                acc[p] = ffma2(hv.x, p0, acc[p]);
                acc[p] = ffma2(hv.y, p1, acc[p]);
            }
        }
        const float SCALE = 0.1f * 0.28209479177387814f * 0.5f; // /sqrt(H)*Y00/sqrt(4)
        int o = tid / CIN;        // 0..1
        int c = tid % CIN;        // 0..22
#pragma unroll
        for (int p = 0; p < RP; p++) {
            float2 v = unpack2(acc[p]);
            g_table[(m0 + 2 * p) * OCP + c * 2 + o]     = v.x * SCALE;
            g_table[(m0 + 2 * p + 1) * OCP + c * 2 + o] = v.y * SCALE;
        }
    }
}

// ---------------------------------------------------------------------------
// Kernel 2: pairwise conv. Interleaved table rows -> float2 loads.
// ---------------------------------------------------------------------------
__global__ void __launch_bounds__(256) conv_kernel(
    const float* __restrict__ features,   // [B,N,23]
    const float* __restrict__ geometry)   // [B,N,3]
{
    __shared__ float feat_s[NB * CIN];
    __shared__ float geo_s[NB * 3];
    __shared__ float red0[256];
    __shared__ float red1[256];

    const int i = blockIdx.x;
    const int b = blockIdx.y;
    const int tid = threadIdx.x;

    const float* fb = features + (size_t)b * NB * CIN;
    const float* gb = geometry + (size_t)b * NB * 3;
    for (int k = tid; k < NB * CIN; k += 256) feat_s[k] = fb[k];
    for (int k = tid; k < NB * 3; k += 256) geo_s[k] = gb[k];
    __syncthreads();

    const float gx = geo_s[i * 3 + 0];
    const float gy = geo_s[i * 3 + 1];
    const float gz = geo_s[i * 3 + 2];

    float acc0 = 0.0f, acc1 = 0.0f;
    for (int j = tid; j < NB; j += 256) {
        float dx = geo_s[j * 3 + 0] - gx;
        float dy = geo_s[j * 3 + 1] - gy;
        float dz = geo_s[j * 3 + 2] - gz;
        float r = sqrtf(fmaf(dx, dx, fmaf(dy, dy, fmaf(dz, dz, 1e-12f))));
        float t = r * INV_DELTA;
        int u = (int)t;
        if (u < NPTS - 1) {            // r >= 4.5 -> R == 0 exactly
            float w = t - (float)u;
            const float2* __restrict__ A = (const float2*)(g_table + u * OCP);
            const float2* __restrict__ Bv = A + (OCP / 2);
            const float* fj = feat_s + j * CIN;
            float d00 = 0.f, d01 = 0.f, d10 = 0.f, d11 = 0.f;
#pragma unroll
            for (int c = 0; c < CIN; c++) {
                float fc = fj[c];
                float2 a = A[c];
                float2 bv = Bv[c];
                d00 = fmaf(a.x,  fc, d00);
                d01 = fmaf(a.y,  fc, d01);
                d10 = fmaf(bv.x, fc, d10);
                d11 = fmaf(bv.y, fc, d11);
            }
            acc0 += fmaf(w, d10 - d00, d00);
            acc1 += fmaf(w, d11 - d01, d01);
        }
    }

    red0[tid] = acc0; red1[tid] = acc1;
    __syncthreads();
#pragma unroll
    for (int s = 128; s > 0; s >>= 1) {
        if (tid < s) { red0[tid] += red0[tid + s]; red1[tid] += red1[tid + s]; }
        __syncthreads();
    }
    if (tid == 0) {
        g_rows[(b * NB + i) * 2 + 0] = fmaxf(red0[0], 0.0f);
        g_rows[(b * NB + i) * 2 + 1] = fmaxf(red1[0], 0.0f);
    }
}

// ---------------------------------------------------------------------------
// Kernel 3: AvgSpacial + final linear.
// ---------------------------------------------------------------------------
__global__ void __launch_bounds__(128) final_kernel(
    const float* __restrict__ lin_w,   // [2]
    const float* __restrict__ lin_b,   // [1]
    float* __restrict__ out)           // [B]
{
    __shared__ float red0[128];
    __shared__ float red1[128];
    const int b = blockIdx.x;
    const int tid = threadIdx.x;
    float s0 = 0.f, s1 = 0.f;
    for (int i = tid; i < NB; i += 128) {
        s0 += g_rows[(b * NB + i) * 2 + 0];
        s1 += g_rows[(b * NB + i) * 2 + 1];
    }
    red0[tid] = s0; red1[tid] = s1;
    __syncthreads();
#pragma unroll
    for (int s = 64; s > 0; s >>= 1) {
        if (tid < s) { red0[tid] += red0[tid + s]; red1[tid] += red1[tid + s]; }
        __syncthreads();
    }
    if (tid == 0) {
        out[b] = (red0[0] * lin_w[0] + red1[0] * lin_w[1]) * (1.0f / (float)NB)
                 + lin_b[0];
    }
}

// ---------------------------------------------------------------------------
extern "C" void kernel_launch(void* const* d_in, const int* in_sizes, int n_in,
                              void* d_out, int out_size) {
    int o = 0;
    if (n_in >= 4 && in_sizes[2] == 1) o = 1;   // num_atoms scalar present

    const float* features = (const float*)d_in[0];
    const float* geometry = (const float*)d_in[1];
    const float* w_in     = (const float*)d_in[2 + o];
    const float* w_h      = (const float*)d_in[3 + o];
    const float* w_out    = (const float*)d_in[4 + o];
    const float* lin_w    = (const float*)d_in[5 + o];
    const float* lin_b    = (const float*)d_in[6 + o];

    const int smem_bytes = 2 * HDIM * HDIM * (int)sizeof(float);  // 80 KB
    cudaFuncSetAttribute(mlp_table_kernel,
                         cudaFuncAttributeMaxDynamicSharedMemorySize, smem_bytes);

    mlp_table_kernel<<<GRID_MLP, 128, smem_bytes>>>(w_in, w_h, w_out);
    conv_kernel<<<dim3(NB, BATCH), 256>>>(features, geometry);
    final_kernel<<<BATCH, 128>>>(lin_w, lin_b, (float*)d_out);
}

// round 3
// speedup vs baseline: 4.9204x; 1.6656x over previous
#include <cuda_runtime.h>
#include <cstdint>

// ---------------------------------------------------------------------------
// SE3Net (all l=0): K(r) is a scalar function of distance, zero for r>=4.5.
// K1: grid MLP. 64 blocks x 400 threads. Thread = (col-pair, j-octant).
//     h kept as row-pair float2 broadcast vectors; weights cp.async
//     double-buffered; per-layer SMEM partial-combine; packed f32x2 FFMA.
// K2: conv. 72 blocks x 256 threads, 16 atoms/block, table+feat+geo in SMEM,
//     16-lane shfl reduction.
// K3: mean + final linear.
// ---------------------------------------------------------------------------

#define NPTS    256
#define OCP     50          // padded interleaved table row stride (floats)
#define CIN     23
#define NB      286
#define BATCH   4
#define HDIM    100
#define HP      104         // padded hidden (zeros in [100,104))
#define NLAYERS 49
#define RMAX    4.5f
#define DELTA   (RMAX / (float)(NPTS - 1))
#define INV_DELTA ((float)(NPTS - 1) / RMAX)

#define TM 4                // grid rows per MLP block
#define GRID_MLP (NPTS / TM)
#define SQ 8                // j-split ways
#define JP (HP / SQ)        // 13 j per split
#define MLP_THREADS 400

typedef unsigned long long ull;

__device__ float g_table[NPTS * OCP];          // [u][c*2 + o]
__device__ float g_rows[BATCH * NB * 2];

__device__ __forceinline__ ull ffma2(ull a, ull b, ull c) {
    ull d;
    asm("fma.rn.f32x2 %0, %1, %2, %3;" : "=l"(d) : "l"(a), "l"(b), "l"(c));
    return d;
}
__device__ __forceinline__ ull add2(ull a, ull b) {
    ull d;
    asm("add.rn.f32x2 %0, %1, %2;" : "=l"(d) : "l"(a), "l"(b));
    return d;
}
__device__ __forceinline__ ull pack2(float lo, float hi) {
    ull d;
    asm("mov.b64 %0, {%1, %2};" : "=l"(d) : "f"(lo), "f"(hi));
    return d;
}
__device__ __forceinline__ float2 unpack2(ull v) {
    float lo, hi;
    asm("mov.b64 {%0, %1}, %2;" : "=f"(lo), "=f"(hi) : "l"(v));
    return make_float2(lo, hi);
}
__device__ __forceinline__ void cp16(void* smem_dst, const void* gptr) {
    uint32_t saddr = (uint32_t)__cvta_generic_to_shared(smem_dst);
    asm volatile("cp.async.cg.shared.global [%0], [%1], 16;"
                 :: "r"(saddr), "l"(gptr) : "memory");
}
__device__ __forceinline__ float bump(float x) {
    float ax = fabsf(x);
    if (ax >= 1.0f) return 0.0f;
    float c = cosf(1.5707963267948966f * x);
    return c * c;
}

// ---------------------------------------------------------------------------
// Kernel 1: grid MLP.
// ---------------------------------------------------------------------------
__global__ void __launch_bounds__(MLP_THREADS) mlp_table_kernel(
    const float* __restrict__ w_in,    // [3,100]
    const float* __restrict__ w_h,     // [49,100,100]
    const float* __restrict__ w_out)   // [100,46]
{
    extern __shared__ float wbuf[];                 // 2 * HP * 100 floats
    __shared__ ull h2[2][2][HP];                    // [buf][rowpair][j]
    __shared__ ull part[SQ][HDIM / 2][2][2];        // [q][c2][colk][p]

    const int tid = threadIdx.x;
    const int m0 = blockIdx.x * TM;
    const int q  = tid / (HDIM / 2);                // j-octant
    const int c2 = tid % (HDIM / 2);                // column pair
    const int j0 = q * JP;

    // zero padding rows of both weight buffers (j in [100,104))
    for (int k = tid; k < 2 * (HP - HDIM) * HDIM; k += MLP_THREADS) {
        int b = k / ((HP - HDIM) * HDIM);
        int rem = k % ((HP - HDIM) * HDIM);
        wbuf[b * HP * HDIM + HDIM * HDIM + rem] = 0.0f;
    }
    // zero h padding
    if (tid < 16) {
        int b = tid / 8, p = (tid / 4) & 1, j = HDIM + (tid & 3);
        h2[b][p][j] = 0ULL;
    }

    // stage layer-0 weights into buf0 (rows 0..99 contiguous)
    for (int k = tid; k < (HDIM * HDIM) / 4; k += MLP_THREADS)
        cp16(wbuf + 4 * k, w_h + 4 * k);
    asm volatile("cp.async.commit_group;" ::: "memory");

    // ---- layer 0: basis -> h ----
    if (tid < HDIM) {
        const float inv_sqrt3 = 0.57735026918962576f;
        float wi0 = w_in[tid], wi1 = w_in[HDIM + tid], wi2 = w_in[2 * HDIM + tid];
        float v[TM];
#pragma unroll
        for (int r = 0; r < TM; r++) {
            float rr = (float)(m0 + r) * DELTA;
            float b0 = bump(rr * (1.0f / 1.5f));
            float b1 = bump((rr - 1.5f) * (1.0f / 1.5f));
            float b2 = bump((rr - 3.0f) * (1.0f / 1.5f));
            float a = (b0 * wi0 + b1 * wi1 + b2 * wi2) * inv_sqrt3;
            v[r] = fmaxf(a, 0.0f);
        }
        h2[0][0][tid] = pack2(v[0], v[1]);
        h2[0][1][tid] = pack2(v[2], v[3]);
    }

    int cur = 0;
#pragma unroll 1
    for (int l = 0; l < NLAYERS; l++) {
        if (l + 1 < NLAYERS) {
            const float* src = w_h + (size_t)(l + 1) * (HDIM * HDIM);
            float* dst = wbuf + ((l + 1) & 1) * (HP * HDIM);
            for (int k = tid; k < (HDIM * HDIM) / 4; k += MLP_THREADS)
                cp16(dst + 4 * k, src + 4 * k);
            asm volatile("cp.async.commit_group;" ::: "memory");
            asm volatile("cp.async.wait_group 1;" ::: "memory");
        } else {
            asm volatile("cp.async.wait_group 0;" ::: "memory");
        }
        __syncthreads();   // weights visible; prev combine's h visible

        const float* __restrict__ ws = wbuf + (l & 1) * (HP * HDIM);
        ull a00 = 0, a01 = 0, a10 = 0, a11 = 0;
#pragma unroll
        for (int jj = 0; jj < JP; jj++) {
            int j = j0 + jj;
            float2 w2 = *reinterpret_cast<const float2*>(ws + j * HDIM + 2 * c2);
            ull pw0 = pack2(w2.x, w2.x);
            ull pw1 = pack2(w2.y, w2.y);
            ull hp0 = h2[cur][0][j];
            ull hp1 = h2[cur][1][j];
            a00 = ffma2(hp0, pw0, a00);
            a01 = ffma2(hp1, pw0, a01);
            a10 = ffma2(hp0, pw1, a10);
            a11 = ffma2(hp1, pw1, a11);
        }
        part[q][c2][0][0] = a00;
        part[q][c2][0][1] = a01;
        part[q][c2][1][0] = a10;
        part[q][c2][1][1] = a11;
        __syncthreads();

        if (tid < HDIM) {
            int cc = tid >> 1, ck = tid & 1;
            ull s0 = part[0][cc][ck][0], s1 = part[0][cc][ck][1];
#pragma unroll
            for (int qq = 1; qq < SQ; qq++) {
                s0 = add2(s0, part[qq][cc][ck][0]);
                s1 = add2(s1, part[qq][cc][ck][1]);
            }
            float2 v0 = unpack2(s0), v1 = unpack2(s1);
            h2[cur ^ 1][0][tid] = pack2(fmaxf(v0.x * 0.1f, 0.0f),
                                        fmaxf(v0.y * 0.1f, 0.0f));
            h2[cur ^ 1][1][tid] = pack2(fmaxf(v1.x * 0.1f, 0.0f),
                                        fmaxf(v1.y * 0.1f, 0.0f));
        }
        cur ^= 1;
        // no sync here: next iteration's __syncthreads covers combine->compute,
        // and the cp.async issued next writes the buffer whose reads finished
        // before the post-compute sync above.
    }
    __syncthreads();

    // ---- output layer: 46 cols x 4 rows = 184 threads ----
    if (tid < 2 * CIN * TM) {
        int o = tid % (2 * CIN);    // output unit 0..45
        int r = tid / (2 * CIN);    // row 0..3
        const float* hrow = reinterpret_cast<const float*>(&h2[cur][r >> 1][0])
                            + (r & 1);
        float acc = 0.0f;
#pragma unroll 4
        for (int j = 0; j < HDIM; j++)
            acc = fmaf(hrow[2 * j], w_out[j * (2 * CIN) + o], acc);
        const float SCALE = 0.1f * 0.28209479177387814f * 0.5f;
        int co = o % CIN, oo = o / CIN;
        g_table[(m0 + r) * OCP + co * 2 + oo] = acc * SCALE;
    }
}

// ---------------------------------------------------------------------------
// Kernel 2: pairwise conv. 16 atoms/block; table+feat+geo in SMEM; shfl reduce.
// ---------------------------------------------------------------------------
#define NBT 16
#define CONV_THREADS 256

__global__ void __launch_bounds__(CONV_THREADS) conv_kernel(
    const float* __restrict__ features,   // [B,N,23]
    const float* __restrict__ geometry)   // [B,N,3]
{
    extern __shared__ float cs[];
    float* table_s = cs;                          // NPTS*OCP
    float* feat_s  = cs + NPTS * OCP;             // NB*CIN
    float* geo_s   = feat_s + NB * CIN;           // NB*3

    const int tid = threadIdx.x;
    const int b = blockIdx.y;
    const int i0 = blockIdx.x * NBT;

    // stage table (float4), features, geometry
    for (int k = tid; k < (NPTS * OCP) / 4; k += CONV_THREADS)
        reinterpret_cast<float4*>(table_s)[k] =
            reinterpret_cast<const float4*>(g_table)[k];
    const float* fb = features + (size_t)b * NB * CIN;
    const float* gb = geometry + (size_t)b * NB * 3;
    for (int k = tid; k < NB * CIN; k += CONV_THREADS) feat_s[k] = fb[k];
    for (int k = tid; k < NB * 3; k += CONV_THREADS)  geo_s[k] = gb[k];
    __syncthreads();

    const int il = tid >> 4;        // local atom 0..15
    const int jt = tid & 15;        // j lane 0..15
    const int i = i0 + il;
    const bool valid = (i < NB);
    float gx = 0.f, gy = 0.f, gz = 0.f;
    if (valid) { gx = geo_s[i * 3]; gy = geo_s[i * 3 + 1]; gz = geo_s[i * 3 + 2]; }

    float acc0 = 0.0f, acc1 = 0.0f;
    for (int j = jt; j < NB; j += 16) {
        float dx = geo_s[j * 3 + 0] - gx;
        float dy = geo_s[j * 3 + 1] - gy;
        float dz = geo_s[j * 3 + 2] - gz;
        float r = sqrtf(fmaf(dx, dx, fmaf(dy, dy, fmaf(dz, dz, 1e-12f))));
        float t = r * INV_DELTA;
        int u = (int)t;
        if (valid && u < NPTS - 1) {
            float w = t - (float)u;
            const float2* __restrict__ A =
                reinterpret_cast<const float2*>(table_s + u * OCP);
            const float2* __restrict__ Bv = A + (OCP / 2);
            const float* fj = feat_s + j * CIN;
            float d00 = 0.f, d01 = 0.f, d10 = 0.f, d11 = 0.f;
#pragma unroll
            for (int c = 0; c < CIN; c++) {
                float fc = fj[c];
                float2 a = A[c];
                float2 bv = Bv[c];
                d00 = fmaf(a.x,  fc, d00);
                d01 = fmaf(a.y,  fc, d01);
                d10 = fmaf(bv.x, fc, d10);
                d11 = fmaf(bv.y, fc, d11);
            }
            acc0 += fmaf(w, d10 - d00, d00);
            acc1 += fmaf(w, d11 - d01, d01);
        }
    }

#pragma unroll
    for (int off = 8; off > 0; off >>= 1) {
        acc0 += __shfl_xor_sync(0xffffffffu, acc0, off, 16);
        acc1 += __shfl_xor_sync(0xffffffffu, acc1, off, 16);
    }
    if (jt == 0 && valid) {
        g_rows[(b * NB + i) * 2 + 0] = fmaxf(acc0, 0.0f);
        g_rows[(b * NB + i) * 2 + 1] = fmaxf(acc1, 0.0f);
    }
}

// ---------------------------------------------------------------------------
// Kernel 3: AvgSpacial + final linear.
// ---------------------------------------------------------------------------
__global__ void __launch_bounds__(128) final_kernel(
    const float* __restrict__ lin_w,
    const float* __restrict__ lin_b,
    float* __restrict__ out)
{
    __shared__ float red0[128];
    __shared__ float red1[128];
    const int b = blockIdx.x;
    const int tid = threadIdx.x;
    float s0 = 0.f, s1 = 0.f;
    for (int i = tid; i < NB; i += 128) {
        s0 += g_rows[(b * NB + i) * 2 + 0];
        s1 += g_rows[(b * NB + i) * 2 + 1];
    }
    red0[tid] = s0; red1[tid] = s1;
    __syncthreads();
#pragma unroll
    for (int s = 64; s > 0; s >>= 1) {
        if (tid < s) { red0[tid] += red0[tid + s]; red1[tid] += red1[tid + s]; }
        __syncthreads();
    }
    if (tid == 0) {
        out[b] = (red0[0] * lin_w[0] + red1[0] * lin_w[1]) * (1.0f / (float)NB)
                 + lin_b[0];
    }
}

// ---------------------------------------------------------------------------
extern "C" void kernel_launch(void* const* d_in, const int* in_sizes, int n_in,
                              void* d_out, int out_size) {
    int o = 0;
    if (n_in >= 4 && in_sizes[2] == 1) o = 1;   // num_atoms scalar present

    const float* features = (const float*)d_in[0];
    const float* geometry = (const float*)d_in[1];
    const float* w_in     = (const float*)d_in[2 + o];
    const float* w_h      = (const float*)d_in[3 + o];
    const float* w_out    = (const float*)d_in[4 + o];
    const float* lin_w    = (const float*)d_in[5 + o];
    const float* lin_b    = (const float*)d_in[6 + o];

    const int mlp_smem  = 2 * HP * HDIM * (int)sizeof(float);            // 83.2 KB
    const int conv_smem = (NPTS * OCP + NB * CIN + NB * 3) * (int)sizeof(float);
    static int configured = 0;
    cudaFuncSetAttribute(mlp_table_kernel,
                         cudaFuncAttributeMaxDynamicSharedMemorySize, mlp_smem);
    cudaFuncSetAttribute(conv_kernel,
                         cudaFuncAttributeMaxDynamicSharedMemorySize, conv_smem);
    (void)configured;

    mlp_table_kernel<<<GRID_MLP, MLP_THREADS, mlp_smem>>>(w_in, w_h, w_out);
    conv_kernel<<<dim3((NB + NBT - 1) / NBT, BATCH), CONV_THREADS, conv_smem>>>(
        features, geometry);
    final_kernel<<<BATCH, 128>>>(lin_w, lin_b, (float*)d_out);
}

// round 4
// speedup vs baseline: 5.3168x; 1.0806x over previous
#include <cuda_runtime.h>
#include <cstdint>

// ---------------------------------------------------------------------------
// SE3Net (all l=0): K(r) is a scalar function of distance, zero for r>=4.5.
// K1: grid MLP, 64 blocks x 400 threads. Weights double-buffered via bulk
//     TMA (cp.async.bulk + mbarrier). Packed f32x2 FFMA; (col-pair, j-octant)
//     thread layout with per-layer SMEM partial combine.
// K2: pairwise conv (f32x2 dot), fused with mean+final-linear epilogue via a
//     per-batch completion counter (deterministic fixed-order reduce).
// ---------------------------------------------------------------------------

#define NPTS    256
#define OCP     50          // interleaved table row stride (floats)
#define CIN     23
#define NB      286
#define BATCH   4
#define HDIM    100
#define HP      104         // padded hidden (zeros in [100,104))
#define NLAYERS 49
#define RMAX    4.5f
#define DELTA   (RMAX / (float)(NPTS - 1))
#define INV_DELTA ((float)(NPTS - 1) / RMAX)

#define TM 4                // grid rows per MLP block
#define GRID_MLP (NPTS / TM)
#define SQ 8                // j-split ways
#define JP (HP / SQ)        // 13 j per split
#define MLP_THREADS 400
#define WB (HP * HDIM)      // padded weight buffer (floats)
#define LAYER_BYTES (HDIM * HDIM * 4)   // 40000

#define NBT 16
#define CONV_THREADS 256
#define NBX ((NB + NBT - 1) / NBT)      // 18

typedef unsigned long long ull;

__device__ float g_table[NPTS * OCP];   // [u][c*2 + o]; pads zeroed by K1
__device__ float g_rows[BATCH * NB * 2];
__device__ int   g_ctr[BATCH];          // completion counters (self-resetting)

__device__ __forceinline__ ull ffma2(ull a, ull b, ull c) {
    ull d;
    asm("fma.rn.f32x2 %0, %1, %2, %3;" : "=l"(d) : "l"(a), "l"(b), "l"(c));
    return d;
}
__device__ __forceinline__ ull add2(ull a, ull b) {
    ull d;
    asm("add.rn.f32x2 %0, %1, %2;" : "=l"(d) : "l"(a), "l"(b));
    return d;
}
__device__ __forceinline__ ull pack2(float lo, float hi) {
    ull d;
    asm("mov.b64 %0, {%1, %2};" : "=l"(d) : "f"(lo), "f"(hi));
    return d;
}
__device__ __forceinline__ float2 unpack2(ull v) {
    float lo, hi;
    asm("mov.b64 {%0, %1}, %2;" : "=f"(lo), "=f"(hi) : "l"(v));
    return make_float2(lo, hi);
}
__device__ __forceinline__ uint32_t s2u(const void* p) {
    return (uint32_t)__cvta_generic_to_shared(p);
}
__device__ __forceinline__ void mbar_init(uint32_t mbar, uint32_t cnt) {
    asm volatile("mbarrier.init.shared.b64 [%0], %1;" :: "r"(mbar), "r"(cnt)
                 : "memory");
}
__device__ __forceinline__ void mbar_expect_tx(uint32_t mbar, uint32_t bytes) {
    asm volatile("mbarrier.arrive.expect_tx.shared.b64 _, [%0], %1;"
                 :: "r"(mbar), "r"(bytes) : "memory");
}
__device__ __forceinline__ void bulk_g2s(uint32_t dst, const void* src,
                                         uint32_t bytes, uint32_t mbar) {
    asm volatile(
        "cp.async.bulk.shared::cta.global.mbarrier::complete_tx::bytes "
        "[%0], [%1], %2, [%3];"
        :: "r"(dst), "l"(src), "r"(bytes), "r"(mbar) : "memory");
}
__device__ __forceinline__ void mbar_wait(uint32_t mbar, uint32_t parity) {
    asm volatile(
        "{\n\t"
        ".reg .pred P;\n"
        "W%=:\n\t"
        "mbarrier.try_wait.parity.acquire.cta.shared::cta.b64 P, [%0], %1, 0x989680;\n\t"
        "@P bra D%=;\n\t"
        "bra W%=;\n"
        "D%=:\n\t"
        "}"
        :: "r"(mbar), "r"(parity) : "memory");
}
__device__ __forceinline__ float bump(float x) {
    float ax = fabsf(x);
    if (ax >= 1.0f) return 0.0f;
    float c = cosf(1.5707963267948966f * x);
    return c * c;
}

// ---------------------------------------------------------------------------
// Kernel 1: grid MLP with bulk-TMA weight pipeline.
// ---------------------------------------------------------------------------
__global__ void __launch_bounds__(MLP_THREADS) mlp_table_kernel(
    const float* __restrict__ w_in,    // [3,100]
    const float* __restrict__ w_h,     // [49,100,100]
    const float* __restrict__ w_out)   // [100,46]
{
    extern __shared__ __align__(16) float wbuf[];   // 2 * WB floats
    __shared__ ull h2[2][2][HP];
    __shared__ ull part[SQ][HDIM / 2][5];           // stride-5 pad (conflicts)
    __shared__ __align__(8) ull mbar[2];

    const int tid = threadIdx.x;
    const int m0 = blockIdx.x * TM;
    const int q  = tid / (HDIM / 2);
    const int c2 = tid % (HDIM / 2);
    const int j0 = q * JP;

    if (tid == 0) {
        mbar_init(s2u(&mbar[0]), 1);
        mbar_init(s2u(&mbar[1]), 1);
    }
    __syncthreads();
    if (tid == 0) {
        mbar_expect_tx(s2u(&mbar[0]), LAYER_BYTES);
        bulk_g2s(s2u(wbuf), w_h, LAYER_BYTES, s2u(&mbar[0]));
        mbar_expect_tx(s2u(&mbar[1]), LAYER_BYTES);
        bulk_g2s(s2u(wbuf + WB), w_h + HDIM * HDIM, LAYER_BYTES, s2u(&mbar[1]));
    }

    // zero padding rows j in [100,104) of both buffers (TMA never writes there)
    for (int k = tid; k < 2 * (HP - HDIM) * HDIM; k += MLP_THREADS) {
        int b = k / ((HP - HDIM) * HDIM);
        int rem = k % ((HP - HDIM) * HDIM);
        wbuf[b * WB + HDIM * HDIM + rem] = 0.0f;
    }
    if (tid < 16) {
        int b = tid / 8, p = (tid / 4) & 1, j = HDIM + (tid & 3);
        h2[b][p][j] = 0ULL;
    }

    // ---- layer 0: basis -> h ----
    if (tid < HDIM) {
        const float inv_sqrt3 = 0.57735026918962576f;
        float wi0 = w_in[tid], wi1 = w_in[HDIM + tid], wi2 = w_in[2 * HDIM + tid];
        float v[TM];
#pragma unroll
        for (int r = 0; r < TM; r++) {
            float rr = (float)(m0 + r) * DELTA;
            float b0 = bump(rr * (1.0f / 1.5f));
            float b1 = bump((rr - 1.5f) * (1.0f / 1.5f));
            float b2 = bump((rr - 3.0f) * (1.0f / 1.5f));
            float a = (b0 * wi0 + b1 * wi1 + b2 * wi2) * inv_sqrt3;
            v[r] = fmaxf(a, 0.0f);
        }
        h2[0][0][tid] = pack2(v[0], v[1]);
        h2[0][1][tid] = pack2(v[2], v[3]);
    }
    __syncthreads();

    int cur = 0;
#pragma unroll 1
    for (int l = 0; l < NLAYERS; l++) {
        const uint32_t mb = s2u(&mbar[l & 1]);
        mbar_wait(mb, (l >> 1) & 1);

        const float* __restrict__ ws = wbuf + (l & 1) * WB;
        ull a00 = 0, a01 = 0, a10 = 0, a11 = 0;
#pragma unroll
        for (int jj = 0; jj < JP; jj++) {
            int j = j0 + jj;
            float2 w2 = *reinterpret_cast<const float2*>(ws + j * HDIM + 2 * c2);
            ull pw0 = pack2(w2.x, w2.x);
            ull pw1 = pack2(w2.y, w2.y);
            ull hp0 = h2[cur][0][j];
            ull hp1 = h2[cur][1][j];
            a00 = ffma2(hp0, pw0, a00);
            a01 = ffma2(hp1, pw0, a01);
            a10 = ffma2(hp0, pw1, a10);
            a11 = ffma2(hp1, pw1, a11);
        }
        part[q][c2][0] = a00;   // k = colk*2 + p
        part[q][c2][1] = a01;
        part[q][c2][2] = a10;
        part[q][c2][3] = a11;
        __syncthreads();        // partials visible; all reads of ws done

        if (tid == 0 && l + 2 < NLAYERS) {
            mbar_expect_tx(mb, LAYER_BYTES);
            bulk_g2s(s2u(const_cast<float*>(ws)),
                     w_h + (size_t)(l + 2) * (HDIM * HDIM), LAYER_BYTES, mb);
        }

        if (tid < HDIM) {
            int cc = tid >> 1, ck = tid & 1;
            ull s0 = part[0][cc][2 * ck + 0];
            ull s1 = part[0][cc][2 * ck + 1];
#pragma unroll
            for (int qq = 1; qq < SQ; qq++) {
                s0 = add2(s0, part[qq][cc][2 * ck + 0]);
                s1 = add2(s1, part[qq][cc][2 * ck + 1]);
            }
            float2 v0 = unpack2(s0), v1 = unpack2(s1);
            h2[cur ^ 1][0][tid] = pack2(fmaxf(v0.x * 0.1f, 0.0f),
                                        fmaxf(v0.y * 0.1f, 0.0f));
            h2[cur ^ 1][1][tid] = pack2(fmaxf(v1.x * 0.1f, 0.0f),
                                        fmaxf(v1.y * 0.1f, 0.0f));
        }
        __syncthreads();        // h visible; part[] reusable
        cur ^= 1;
    }

    // ---- output layer: 46 cols x 4 rows = 184 threads ----
    if (tid < 2 * CIN * TM) {
        int o = tid % (2 * CIN);
        int r = tid / (2 * CIN);
        const float* hrow = reinterpret_cast<const float*>(&h2[cur][r >> 1][0])
                            + (r & 1);
        float acc = 0.0f;
#pragma unroll 4
        for (int j = 0; j < HDIM; j++)
            acc = fmaf(hrow[2 * j], w_out[j * (2 * CIN) + o], acc);
        const float SCALE = 0.1f * 0.28209479177387814f * 0.5f;
        int co = o % CIN, oo = o / CIN;
        g_table[(m0 + r) * OCP + co * 2 + oo] = acc * SCALE;
    } else if (tid < 2 * CIN * TM + 16) {
        // zero the 4 pad floats of each of this block's 4 table rows
        int z = tid - 2 * CIN * TM;        // 0..15
        int r = z >> 2, pos = 2 * CIN + (z & 3);
        g_table[(m0 + r) * OCP + pos] = 0.0f;
    }
}

// ---------------------------------------------------------------------------
// Kernel 2: pairwise conv + fused mean/final-linear epilogue.
// ---------------------------------------------------------------------------
__global__ void __launch_bounds__(CONV_THREADS) conv_kernel(
    const float* __restrict__ features,   // [B,N,23]
    const float* __restrict__ geometry,   // [B,N,3]
    const float* __restrict__ lin_w,      // [2]
    const float* __restrict__ lin_b,      // [1]
    float* __restrict__ out)              // [B]
{
    extern __shared__ float cs[];
    float* table_s = cs;                          // NPTS*OCP
    float* feat_s  = cs + NPTS * OCP;             // NB*CIN
    float* geo_s   = feat_s + NB * CIN;           // NB*3
    __shared__ float red0[CONV_THREADS];
    __shared__ float red1[CONV_THREADS];
    __shared__ int last_flag;

    const int tid = threadIdx.x;
    const int b = blockIdx.y;
    const int i0 = blockIdx.x * NBT;

    for (int k = tid; k < (NPTS * OCP) / 2; k += CONV_THREADS)
        reinterpret_cast<float2*>(table_s)[k] =
            reinterpret_cast<const float2*>(g_table)[k];
    const float* fb = features + (size_t)b * NB * CIN;
    const float* gb = geometry + (size_t)b * NB * 3;
    for (int k = tid; k < NB * CIN; k += CONV_THREADS) feat_s[k] = fb[k];
    for (int k = tid; k < NB * 3; k += CONV_THREADS)  geo_s[k] = gb[k];
    __syncthreads();

    const int il = tid >> 4;        // local atom 0..15
    const int jt = tid & 15;        // j lane 0..15
    const int i = i0 + il;
    const bool valid = (i < NB);
    float gx = 0.f, gy = 0.f, gz = 0.f;
    if (valid) { gx = geo_s[i * 3]; gy = geo_s[i * 3 + 1]; gz = geo_s[i * 3 + 2]; }

    ull acc = 0ULL;                 // (o0,o1) packed accumulator
    for (int j = jt; j < NB; j += 16) {
        float dx = geo_s[j * 3 + 0] - gx;
        float dy = geo_s[j * 3 + 1] - gy;
        float dz = geo_s[j * 3 + 2] - gz;
        float r = sqrtf(fmaf(dx, dx, fmaf(dy, dy, fmaf(dz, dz, 1e-12f))));
        float t = r * INV_DELTA;
        int u = (int)t;
        if (valid && u < NPTS - 1) {
            float w = t - (float)u;
            const ull* __restrict__ A =
                reinterpret_cast<const ull*>(table_s + u * OCP);
            const ull* __restrict__ Bv = A + (OCP / 2);
            const float* fj = feat_s + j * CIN;
            ull dA = 0ULL, dB = 0ULL;
#pragma unroll
            for (int c = 0; c < CIN; c++) {
                ull fcp = pack2(fj[c], fj[c]);
                dA = ffma2(A[c],  fcp, dA);
                dB = ffma2(Bv[c], fcp, dB);
            }
            acc = ffma2(dA, pack2(1.0f - w, 1.0f - w), acc);
            acc = ffma2(dB, pack2(w, w), acc);
        }
    }

    float2 av = unpack2(acc);
    float acc0 = av.x, acc1 = av.y;
#pragma unroll
    for (int off = 8; off > 0; off >>= 1) {
        acc0 += __shfl_xor_sync(0xffffffffu, acc0, off, 16);
        acc1 += __shfl_xor_sync(0xffffffffu, acc1, off, 16);
    }
    if (jt == 0 && valid) {
        g_rows[(b * NB + i) * 2 + 0] = fmaxf(acc0, 0.0f);
        g_rows[(b * NB + i) * 2 + 1] = fmaxf(acc1, 0.0f);
    }

    // ---- fused epilogue: last block of this batch does mean + linear ----
    __threadfence();
    __syncthreads();
    if (tid == 0)
        last_flag = (atomicAdd(&g_ctr[b], 1) == NBX - 1) ? 1 : 0;
    __syncthreads();
    if (last_flag) {
        __threadfence();            // acquire other blocks' g_rows
        float s0 = 0.f, s1 = 0.f;
        for (int k = tid; k < NB; k += CONV_THREADS) {
            s0 += g_rows[(b * NB + k) * 2 + 0];
            s1 += g_rows[(b * NB + k) * 2 + 1];
        }
        red0[tid] = s0; red1[tid] = s1;
        __syncthreads();
#pragma unroll
        for (int s = CONV_THREADS / 2; s > 0; s >>= 1) {
            if (tid < s) { red0[tid] += red0[tid + s]; red1[tid] += red1[tid + s]; }
            __syncthreads();
        }
        if (tid == 0) {
            out[b] = (red0[0] * lin_w[0] + red1[0] * lin_w[1])
                     * (1.0f / (float)NB) + lin_b[0];
            g_ctr[b] = 0;           // reset for next graph replay
        }
    }
}

// ---------------------------------------------------------------------------
extern "C" void kernel_launch(void* const* d_in, const int* in_sizes, int n_in,
                              void* d_out, int out_size) {
    int o = 0;
    if (n_in >= 4 && in_sizes[2] == 1) o = 1;   // num_atoms scalar present

    const float* features = (const float*)d_in[0];
    const float* geometry = (const float*)d_in[1];
    const float* w_in     = (const float*)d_in[2 + o];
    const float* w_h      = (const float*)d_in[3 + o];
    const float* w_out    = (const float*)d_in[4 + o];
    const float* lin_w    = (const float*)d_in[5 + o];
    const float* lin_b    = (const float*)d_in[6 + o];

    const int mlp_smem  = 2 * WB * (int)sizeof(float);                     // 83.2 KB
    const int conv_smem = (NPTS * OCP + NB * CIN + NB * 3) * (int)sizeof(float);
    cudaFuncSetAttribute(mlp_table_kernel,
                         cudaFuncAttributeMaxDynamicSharedMemorySize, mlp_smem);
    cudaFuncSetAttribute(conv_kernel,
                         cudaFuncAttributeMaxDynamicSharedMemorySize, conv_smem);

    mlp_table_kernel<<<GRID_MLP, MLP_THREADS, mlp_smem>>>(w_in, w_h, w_out);
    conv_kernel<<<dim3(NBX, BATCH), CONV_THREADS, conv_smem>>>(
        features, geometry, lin_w, lin_b, (float*)d_out);
}